// round 11
// baseline (speedup 1.0000x reference)
#include <cuda_runtime.h>

// CrossCompress: B=16384 rows, D=128.
// item_out   = v*(e.w_vv) + e*(v.w_ev) + bias_v
// entity_out = v*(e.w_ve) + e*(v.w_ee) + bias_e
//
// R11: 256-bit memory ops (sm_100-family PTX v8.f32 ld/st). Each lane owns
// 8 contiguous floats; 16 lanes cover a row. Warp = 2 half-warps x 2 rows
// each (4 rows/warp, grid 1024 like R3). Halves every LDG/STG instruction
// (22 -> 14 LSU ops/warp) and halves L1tex queue entries; reduction is a
// 4-level butterfly within 16-lane halves (32 SHFL/warp vs 80).

#define B_ROWS 16384
#define D_DIM  128

__device__ __forceinline__ void ldg256(const float* __restrict__ p, float r[8]) {
    asm volatile("ld.global.nc.v8.f32 {%0,%1,%2,%3,%4,%5,%6,%7}, [%8];"
                 : "=f"(r[0]), "=f"(r[1]), "=f"(r[2]), "=f"(r[3]),
                   "=f"(r[4]), "=f"(r[5]), "=f"(r[6]), "=f"(r[7])
                 : "l"(p));
}

__device__ __forceinline__ void stg256(float* __restrict__ p, const float r[8]) {
    asm volatile("st.global.v8.f32 [%0], {%1,%2,%3,%4,%5,%6,%7,%8};"
                 :: "l"(p),
                    "f"(r[0]), "f"(r[1]), "f"(r[2]), "f"(r[3]),
                    "f"(r[4]), "f"(r[5]), "f"(r[6]), "f"(r[7])
                 : "memory");
}

__global__ __launch_bounds__(128)
void crosscompress_kernel(const float* __restrict__ v_in,
                          const float* __restrict__ e_in,
                          const float* __restrict__ w_vv,
                          const float* __restrict__ w_ve,
                          const float* __restrict__ w_ev,
                          const float* __restrict__ w_ee,
                          const float* __restrict__ bias_v,
                          const float* __restrict__ bias_e,
                          float* __restrict__ out_item,
                          float* __restrict__ out_ent)
{
    const int gtid = blockIdx.x * blockDim.x + threadIdx.x;
    const int warp = gtid >> 5;
    const int lane = gtid & 31;
    const int half = lane >> 4;         // 0 or 1: which row pair
    const int l    = lane & 15;         // position within row (8 floats each)

    const int rowA = warp * 4 + half * 2;
    const int rowB = rowA + 1;
    const int off  = l * 8;             // float offset within a row

    // Batched 256-bit data loads: 4 LDG.256 per lane (= bytes of 8 LDG.128)
    float vA[8], eA[8], vB[8], eB[8];
    ldg256(v_in + rowA * D_DIM + off, vA);
    ldg256(e_in + rowA * D_DIM + off, eA);
    ldg256(v_in + rowB * D_DIM + off, vB);
    ldg256(e_in + rowB * D_DIM + off, eB);

    // Weights/biases: 256-bit L1-resident loads
    float wvv[8], wev[8], wve[8], wee[8], bv[8], be[8];
    ldg256(w_vv + off, wvv);
    ldg256(w_ev + off, wev);
    ldg256(w_ve + off, wve);
    ldg256(w_ee + off, wee);
    ldg256(bias_v + off, bv);
    ldg256(bias_e + off, be);

    // Per-lane partial dots (8 independent accumulator chains)
    float dvvA = 0.f, devA = 0.f, dveA = 0.f, deeA = 0.f;
    float dvvB = 0.f, devB = 0.f, dveB = 0.f, deeB = 0.f;
    #pragma unroll
    for (int i = 0; i < 8; i++) {
        dvvA += eA[i] * wvv[i];  devA += vA[i] * wev[i];
        dveA += eA[i] * wve[i];  deeA += vA[i] * wee[i];
        dvvB += eB[i] * wvv[i];  devB += vB[i] * wev[i];
        dveB += eB[i] * wve[i];  deeB += vB[i] * wee[i];
    }

    // 4-level butterfly within each 16-lane half (offsets 1,2,4,8).
    // XOR with offset < 16 never crosses the half boundary.
    #pragma unroll
    for (int o = 1; o <= 8; o <<= 1) {
        dvvA += __shfl_xor_sync(0xFFFFFFFFu, dvvA, o);
        devA += __shfl_xor_sync(0xFFFFFFFFu, devA, o);
        dveA += __shfl_xor_sync(0xFFFFFFFFu, dveA, o);
        deeA += __shfl_xor_sync(0xFFFFFFFFu, deeA, o);
        dvvB += __shfl_xor_sync(0xFFFFFFFFu, dvvB, o);
        devB += __shfl_xor_sync(0xFFFFFFFFu, devB, o);
        dveB += __shfl_xor_sync(0xFFFFFFFFu, dveB, o);
        deeB += __shfl_xor_sync(0xFFFFFFFFu, deeB, o);
    }

    // Combine + 256-bit stores (4 STG.256 per lane)
    float oiA[8], oeA[8], oiB[8], oeB[8];
    #pragma unroll
    for (int i = 0; i < 8; i++) {
        oiA[i] = vA[i] * dvvA + eA[i] * devA + bv[i];
        oeA[i] = vA[i] * dveA + eA[i] * deeA + be[i];
        oiB[i] = vB[i] * dvvB + eB[i] * devB + bv[i];
        oeB[i] = vB[i] * dveB + eB[i] * deeB + be[i];
    }
    stg256(out_item + rowA * D_DIM + off, oiA);
    stg256(out_ent  + rowA * D_DIM + off, oeA);
    stg256(out_item + rowB * D_DIM + off, oiB);
    stg256(out_ent  + rowB * D_DIM + off, oeB);
}

extern "C" void kernel_launch(void* const* d_in, const int* in_sizes, int n_in,
                              void* d_out, int out_size)
{
    const float* v_in   = (const float*)d_in[0];
    const float* e_in   = (const float*)d_in[1];
    const float* w_vv   = (const float*)d_in[2];
    const float* w_ve   = (const float*)d_in[3];
    const float* w_ev   = (const float*)d_in[4];
    const float* w_ee   = (const float*)d_in[5];
    const float* bias_v = (const float*)d_in[6];
    const float* bias_e = (const float*)d_in[7];

    float* out = (float*)d_out;
    float* out_item = out;
    float* out_ent  = out + B_ROWS * D_DIM;

    // 4 warps/block, 4 rows/warp -> 16 rows/block -> 1024 blocks
    const int threads = 128;
    const int blocks  = B_ROWS / 16;   // 1024

    crosscompress_kernel<<<blocks, threads>>>(v_in, e_in, w_vv, w_ve, w_ev, w_ee,
                                              bias_v, bias_e, out_item, out_ent);
}